// round 1
// baseline (speedup 1.0000x reference)
#include <cuda_runtime.h>
#include <math.h>

#define KNOTS 1024
#define SAMPLES 4096
#define S_PTS 4095           // SAMPLES - 1
#define KCHUNKS 16           // k-split in final pass
#define STILE 128

// ---------------- scratch (device globals; no allocation allowed) ------------
__device__ float g_smear[(size_t)KNOTS * S_PTS];   // 16.7 MB
__device__ float g_A[KNOTS];
__device__ float g_B[KNOTS];
__device__ float g_cB[KNOTS];       // cos(pol)*B
__device__ float g_sin[KNOTS];      // sin(pol)
__device__ float g_erl[KNOTS], g_erh[KNOTS];   // exp(-ent_low), exp(-ent_high)
__device__ float g_rl[KNOTS],  g_rh[KNOTS];    // exp(-knot_low), exp(-knot_high)
__device__ float g_xlow[KNOTS], g_xstep[KNOTS];
__device__ float g_grl[KNOTS], g_grh[KNOTS];   // exp(-lows), exp(-highs) for envelope
__device__ float g_glow[KNOTS], g_gd[KNOTS];   // lows, (highs-lows)
__device__ float g_rowsum[KNOTS], g_coef1[KNOTS], g_cw[KNOTS], g_w[KNOTS];
__device__ float g_penv[KCHUNKS * S_PTS];
__device__ float g_pres[KCHUNKS * S_PTS];

__device__ __forceinline__ float block_reduce_256(float v, float* sh) {
    int tid = threadIdx.x;
    // warp reduce
    #pragma unroll
    for (int o = 16; o > 0; o >>= 1) v += __shfl_xor_sync(0xFFFFFFFFu, v, o);
    if ((tid & 31) == 0) sh[tid >> 5] = v;
    __syncthreads();
    if (tid < 8) {
        v = sh[tid];
        #pragma unroll
        for (int o = 4; o > 0; o >>= 1) v += __shfl_xor_sync(0xFFu, v, o);
    }
    return v;  // valid in tid 0
}

// ---------------- K0: per-knot precompute ------------------------------------
__global__ void k0_precompute(const float* __restrict__ x,
                              const float* __restrict__ sw,
                              const float* __restrict__ kmean,
                              const float* __restrict__ klow,
                              const float* __restrict__ khigh,
                              const float* __restrict__ elow,
                              const float* __restrict__ ehigh,
                              const float* __restrict__ pol) {
    int k = blockIdx.x * blockDim.x + threadIdx.x;
    if (k >= KNOTS) return;
    float lower = sw[0], upper = sw[1];
    float xk = x[k];
    float xlow = (1.0f - lower) * xk;
    g_xlow[k]  = xlow;
    g_xstep[k] = (upper - lower) * xk * (1.0f / (float)SAMPLES);

    float rl = __expf(-klow[k]);
    float rh = __expf(-khigh[k]);
    g_rl[k] = rl; g_rh[k] = rh;

    // B[k] = S * smear[k, 0]  (grid at s=0 is x_low)
    float mean = kmean[k];
    float d = xlow - mean;
    float r = (xlow <= mean) ? rl : rh;
    float a = d * r;
    float B = (float)S_PTS * __expf(-0.5f * a * a);
    g_B[k] = B;

    float p = pol[k];
    g_cB[k]  = cosf(p) * B;
    g_sin[k] = sinf(p);

    g_erl[k] = __expf(-elow[k]);
    g_erh[k] = __expf(-ehigh[k]);

    // trailing gaussian envelope params
    float lows  = xlow;                 // (1-lower)*x
    float highs = (1.0f + upper) * xk;
    g_glow[k] = lows;
    g_gd[k]   = highs - lows;
    g_grl[k]  = __expf(-lows);
    g_grh[k]  = __expf(-highs);

    g_cw[k] = 0.0f;   // zero for K2 atomics (re-done every replay)
}

// ---------------- K1: smear[k, :] + A[k] -------------------------------------
__global__ __launch_bounds__(256) void k1_smear(const float* __restrict__ kmean) {
    int k = blockIdx.x;
    float xlow  = g_xlow[k];
    float xstep = g_xstep[k];
    float mean  = kmean[k];
    float rl = g_rl[k], rh = g_rh[k];
    float* __restrict__ row = &g_smear[(size_t)k * S_PTS];

    float acc = 0.0f;
    for (int s = threadIdx.x; s < S_PTS; s += 256) {
        float xi = (float)s * (1.0f / (float)SAMPLES);
        float gv = fmaf(xstep, xi, xlow);
        float d  = gv - mean;
        float r  = (gv <= mean) ? rl : rh;
        float a  = d * r;
        float v  = __expf(-0.5f * a * a);
        row[s] = v;
        acc += v;
    }
    __shared__ float sh[8];
    float tot = block_reduce_256(acc, sh);
    if (threadIdx.x == 0) g_A[k] = tot;
}

// ---------------- K2: mix matrix reductions ----------------------------------
__global__ __launch_bounds__(256) void k2_mix(const float* __restrict__ emean) {
    int i = blockIdx.x;
    float AiS = g_A[i] * (1.0f / (float)S_PTS);
    float Bi  = g_B[i];

    float rs = 0.0f, c1 = 0.0f;
    for (int j = threadIdx.x; j < KNOTS; j += 256) {
        float corr = AiS * g_A[j];
        float em = emean[j];
        float d = corr - em;
        float r = (corr <= em) ? g_erl[j] : g_erh[j];
        float a = d * r;
        float m = __expf(-0.5f * a * a);
        if (j == i) m = 0.0f;
        rs += m;
        c1 += m * g_cB[j];
        float v = Bi * m;
        if (v != 0.0f) atomicAdd(&g_cw[j], v);
    }
    __shared__ float sh1[8], sh2[8];
    float trs = block_reduce_256(rs, sh1);
    __syncthreads();
    float tc1 = block_reduce_256(c1, sh2);
    if (threadIdx.x == 0) { g_rowsum[i] = trs; g_coef1[i] = tc1; }
}

// ---------------- K3: combine per-knot weights -------------------------------
__global__ void k3_weights() {
    int k = blockIdx.x * blockDim.x + threadIdx.x;
    if (k >= KNOTS) return;
    g_w[k] = g_coef1[k] + (float)(KNOTS - 1) - g_rowsum[k] + g_sin[k] * g_cw[k];
}

// ---------------- K4: envelope + weighted smear, partial over k-chunks -------
__global__ __launch_bounds__(STILE) void k4_combine(const float* __restrict__ x) {
    int s  = blockIdx.x * STILE + threadIdx.x;
    int kc = blockIdx.y * (KNOTS / KCHUNKS);
    bool ok = (s < S_PTS);
    int si = ok ? s : 0;
    float xi = (float)s * (1.0f / (float)SAMPLES);

    float env = 0.0f, res = 0.0f;
    #pragma unroll 4
    for (int k = kc; k < kc + (KNOTS / KCHUNKS); k++) {
        float mean = x[k];
        float gv = fmaf(g_gd[k], xi, g_glow[k]);
        float d  = gv - mean;
        float r  = (gv <= mean) ? g_grl[k] : g_grh[k];
        float a  = d * r;
        env += __expf(-0.5f * a * a);
        res = fmaf(g_w[k], g_smear[(size_t)k * S_PTS + si], res);
    }
    if (ok) {
        g_penv[blockIdx.y * S_PTS + s] = env;
        g_pres[blockIdx.y * S_PTS + s] = res;
    }
}

// ---------------- K5: final reduce + multiply --------------------------------
__global__ void k5_final(float* __restrict__ out) {
    int s = blockIdx.x * blockDim.x + threadIdx.x;
    if (s >= S_PTS) return;
    float e = 0.0f, r = 0.0f;
    #pragma unroll
    for (int y = 0; y < KCHUNKS; y++) {
        e += g_penv[y * S_PTS + s];
        r += g_pres[y * S_PTS + s];
    }
    out[s] = e * r;
}

// ---------------- launch ------------------------------------------------------
extern "C" void kernel_launch(void* const* d_in, const int* in_sizes, int n_in,
                              void* d_out, int out_size) {
    const float* x     = (const float*)d_in[0];
    const float* sw    = (const float*)d_in[1];
    const float* kmean = (const float*)d_in[2];
    const float* klow  = (const float*)d_in[3];
    const float* khigh = (const float*)d_in[4];
    const float* emean = (const float*)d_in[5];
    const float* elow  = (const float*)d_in[6];
    const float* ehigh = (const float*)d_in[7];
    const float* pol   = (const float*)d_in[8];
    float* out = (float*)d_out;

    k0_precompute<<<(KNOTS + 255) / 256, 256>>>(x, sw, kmean, klow, khigh, elow, ehigh, pol);
    k1_smear<<<KNOTS, 256>>>(kmean);
    k2_mix<<<KNOTS, 256>>>(emean);
    k3_weights<<<(KNOTS + 255) / 256, 256>>>();
    dim3 g4((S_PTS + STILE - 1) / STILE, KCHUNKS);
    k4_combine<<<g4, STILE>>>(x);
    k5_final<<<(S_PTS + 255) / 256, 256>>>(out);
}

// round 2
// speedup vs baseline: 1.7686x; 1.7686x over previous
#include <cuda_runtime.h>
#include <math.h>

#define KNOTS 1024
#define SAMPLES 4096
#define S_PTS 4095
#define INV_SAMP (1.0f / 4096.0f)
#define NMOM 10   // Taylor terms n = 0..9

// ---------------- scratch (device globals; no allocation allowed) ------------
__device__ float g_smear[(size_t)KNOTS * S_PTS];   // only used on general fallback
__device__ float g_A[KNOTS], g_B[KNOTS];
__device__ float g_cB[KNOTS], g_sin[KNOTS];
__device__ float g_erl[KNOTS], g_erh[KNOTS];
__device__ float g_v0[KNOTS], g_isconst[KNOTS];
__device__ float g_clo[KNOTS], g_chi[KNOTS];
__device__ float g_glow[KNOTS], g_gd[KNOTS], g_grl[KNOTS], g_grh[KNOTS];
__device__ float g_rowsum[KNOTS], g_coef1[KNOTS], g_cw[KNOTS], g_w[KNOTS];
__device__ float g_envcoef[2 * NMOM];   // [side][n] = M_n(side)/n!
__device__ float g_Rconst;
__device__ int   g_fastenv, g_anyvar;

// ---------------- reductions --------------------------------------------------
__device__ __forceinline__ float warp_sum(float v) {
    #pragma unroll
    for (int o = 16; o > 0; o >>= 1) v += __shfl_xor_sync(0xFFFFFFFFu, v, o);
    return v;
}
__device__ __forceinline__ float block_sum(float v, float* sh) {
    int tid = threadIdx.x;
    v = warp_sum(v);
    if ((tid & 31) == 0) sh[tid >> 5] = v;
    __syncthreads();
    float r = 0.0f;
    int nw = (blockDim.x + 31) >> 5;
    if (tid < 32) {
        r = (tid < nw) ? sh[tid] : 0.0f;
        r = warp_sum(r);
    }
    __syncthreads();
    return r;  // valid in tid 0
}
__device__ __forceinline__ float block_max(float v, float* sh) {
    int tid = threadIdx.x;
    #pragma unroll
    for (int o = 16; o > 0; o >>= 1) v = fmaxf(v, __shfl_xor_sync(0xFFFFFFFFu, v, o));
    if ((tid & 31) == 0) sh[tid >> 5] = v;
    __syncthreads();
    float r = -1e30f;
    int nw = (blockDim.x + 31) >> 5;
    if (tid < 32) {
        r = (tid < nw) ? sh[tid] : -1e30f;
        #pragma unroll
        for (int o = 16; o > 0; o >>= 1) r = fmaxf(r, __shfl_xor_sync(0xFFFFFFFFu, r, o));
    }
    __syncthreads();
    return r;
}

// ---------------- K1: per-knot params + (fallback) smear row -----------------
__global__ __launch_bounds__(128) void k_prep(const float* __restrict__ x,
                                              const float* __restrict__ sw,
                                              const float* __restrict__ kmean,
                                              const float* __restrict__ klow,
                                              const float* __restrict__ khigh,
                                              const float* __restrict__ elow,
                                              const float* __restrict__ ehigh,
                                              const float* __restrict__ pol) {
    __shared__ float s_xlow, s_xstep, s_mean, s_rl, s_rh;
    __shared__ int s_const;
    int k = blockIdx.x;

    if (threadIdx.x == 0) {
        float lower = sw[0], upper = sw[1];
        float xk = x[k];
        float xlow  = (1.0f - lower) * xk;
        float xstep = ((upper - lower) * xk) * INV_SAMP;
        float rl = __expf(-klow[k]);
        float rh = __expf(-khigh[k]);
        float mean = kmean[k];

        // smear at s=0 (grid value is exactly xlow)
        float d  = xlow - mean;
        float r0 = (xlow <= mean) ? rl : rh;
        float a0 = d * r0;
        float v0 = __expf(-0.5f * a0 * a0);
        float B  = (float)S_PTS * v0;

        float sp, cp;
        __sincosf(pol[k], &sp, &cp);

        bool cst = (xstep == 0.0f);
        g_isconst[k] = cst ? 1.0f : 0.0f;
        g_v0[k] = v0;
        g_B[k]  = B;
        g_cB[k] = cp * B;
        g_sin[k] = sp;
        g_erl[k] = __expf(-elow[k]);
        g_erh[k] = __expf(-ehigh[k]);
        g_cw[k] = 0.0f;
        if (cst) g_A[k] = (float)S_PTS * v0;

        // envelope params
        float lows  = xlow;                  // (1-lower)*x
        float highs = (1.0f + upper) * xk;
        float erlw = __expf(-lows);
        float erhg = __expf(-highs);
        g_glow[k] = lows;
        g_gd[k]   = highs - lows;
        g_grl[k]  = erlw;
        g_grh[k]  = erhg;
        float hlo = xk * erlw, hhi = xk * erhg;
        g_clo[k] = 0.5f * hlo * hlo;
        g_chi[k] = 0.5f * hhi * hhi;

        s_xlow = xlow; s_xstep = xstep; s_mean = mean; s_rl = rl; s_rh = rh;
        s_const = cst ? 1 : 0;
    }
    __syncthreads();
    if (s_const) return;   // fast path: constant smear row, A already set

    // general fallback: materialize smear row + reduce A
    float xlow = s_xlow, xstep = s_xstep, mean = s_mean, rl = s_rl, rh = s_rh;
    float* __restrict__ row = &g_smear[(size_t)k * S_PTS];
    float acc = 0.0f;
    for (int s = threadIdx.x; s < S_PTS; s += 128) {
        float gv = fmaf(xstep, (float)s, xlow);   // xstep already has /SAMPLES folded via *xi? no:
        // careful: reference grid = xstep * (s/SAMPLES) + xlow, with xstep = (u-l)x/SAMPLES.
        // here s_xstep = (u-l)x/SAMPLES, so gv = s_xstep * (s/SAMPLES)... recompute properly:
        gv = fmaf(xstep, (float)s * INV_SAMP, xlow);
        float d = gv - mean;
        float r = (gv <= mean) ? rl : rh;
        float a = d * r;
        float v = __expf(-0.5f * a * a);
        row[s] = v;
        acc += v;
    }
    __shared__ float sh[4];
    float tot = block_sum(acc, sh);
    if (threadIdx.x == 0) g_A[k] = tot;
}

// ---------------- K2: mix-matrix reductions (underflow-guarded) --------------
__global__ __launch_bounds__(256) void k_mix(const float* __restrict__ emean) {
    int i = blockIdx.x;
    float AiS = g_A[i] * (1.0f / (float)S_PTS);
    float Bi  = g_B[i];

    float rs = 0.0f, c1 = 0.0f;
    #pragma unroll
    for (int jj = 0; jj < KNOTS / 256; jj++) {
        int j = jj * 256 + threadIdx.x;
        float corr = AiS * g_A[j];
        float em = emean[j];
        float d = corr - em;
        float r = (corr <= em) ? g_erl[j] : g_erh[j];
        float a = d * r;
        float e = 0.5f * a * a;
        float m = 0.0f;
        if (e < 88.0f) m = __expf(-e);        // exp underflows to 0 beyond this anyway
        if (j == i) m = 0.0f;
        rs += m;
        c1 += m * g_cB[j];
        float v = Bi * m;
        if (v != 0.0f) atomicAdd(&g_cw[j], v);
    }
    __shared__ float sh[8];
    float trs = block_sum(rs, sh);
    float tc1 = block_sum(c1, sh);
    if (threadIdx.x == 0) { g_rowsum[i] = trs; g_coef1[i] = tc1; }
}

// ---------------- K3: weights + envelope moments + flags ----------------------
__global__ __launch_bounds__(1024) void k_reduce(const float* __restrict__ sw) {
    __shared__ float sh[32];
    int k = threadIdx.x;

    float w = g_coef1[k] + (float)(KNOTS - 1) - g_rowsum[k] + g_sin[k] * g_cw[k];
    g_w[k] = w;

    float isc = g_isconst[k];
    float rc = isc * w * g_v0[k];
    float Rc = block_sum(rc, sh);

    float nvar = 1.0f - isc;
    float anyv = block_sum(nvar, sh);

    float clo = g_clo[k], chi = g_chi[k];
    float cmax = block_max(fmaxf(clo, chi), sh);

    // moments M_n = sum_k c^n, n = 1..9 (M_0 = K)
    float pl = 1.0f, ph = 1.0f;
    const float invfact[NMOM] = {1.0f, 1.0f, 0.5f, 1.0f/6.0f, 1.0f/24.0f, 1.0f/120.0f,
                                 1.0f/720.0f, 1.0f/5040.0f, 1.0f/40320.0f, 1.0f/362880.0f};
    #pragma unroll
    for (int n = 1; n < NMOM; n++) {
        pl *= clo; ph *= chi;
        float Ml = block_sum(pl, sh);
        float Mh = block_sum(ph, sh);
        if (k == 0) {
            g_envcoef[n]        = Ml * invfact[n];
            g_envcoef[NMOM + n] = Mh * invfact[n];
        }
    }
    if (k == 0) {
        g_envcoef[0] = (float)KNOTS;
        g_envcoef[NMOM] = (float)KNOTS;
        g_Rconst = Rc;
        g_anyvar = (anyv > 0.0f) ? 1 : 0;
        float lower = sw[0], upper = sw[1];
        float phi0 = -lower;
        float phiE = fmaf((float)(S_PTS - 1) * INV_SAMP, lower + upper, -lower);
        float tmax = fmaxf(phi0 * phi0, phiE * phiE);
        float gate = cmax * tmax;
        g_fastenv = (gate <= 1.0f) ? 1 : 0;   // NaN -> fallback
    }
}

// ---------------- K4: output ---------------------------------------------------
__global__ __launch_bounds__(128) void k_out(const float* __restrict__ x,
                                             const float* __restrict__ sw,
                                             float* __restrict__ out) {
    int s = blockIdx.x * 128 + threadIdx.x;
    if (s >= S_PTS) return;

    float lower = sw[0], upper = sw[1];
    float xi = (float)s * INV_SAMP;
    float phi = fmaf(xi, lower + upper, -lower);
    int side = (phi <= 0.0f) ? 0 : 1;
    float t = phi * phi;

    float env;
    if (g_fastenv) {
        const float* cf = g_envcoef + side * NMOM;
        float u = -t;
        env = cf[NMOM - 1];
        #pragma unroll
        for (int n = NMOM - 2; n >= 0; n--) env = fmaf(env, u, cf[n]);
    } else {
        env = 0.0f;
        for (int k = 0; k < KNOTS; k++) {
            float mean = x[k];
            float gv = fmaf(g_gd[k], xi, g_glow[k]);
            float d = gv - mean;
            float r = (gv <= mean) ? g_grl[k] : g_grh[k];
            float a = d * r;
            env += __expf(-0.5f * a * a);
        }
    }

    float res = g_Rconst;
    if (g_anyvar) {
        for (int k = 0; k < KNOTS; k++) {
            if (g_isconst[k] == 0.0f)
                res = fmaf(g_w[k], g_smear[(size_t)k * S_PTS + s], res);
        }
    }
    out[s] = env * res;
}

// ---------------- launch ------------------------------------------------------
extern "C" void kernel_launch(void* const* d_in, const int* in_sizes, int n_in,
                              void* d_out, int out_size) {
    const float* x     = (const float*)d_in[0];
    const float* sw    = (const float*)d_in[1];
    const float* kmean = (const float*)d_in[2];
    const float* klow  = (const float*)d_in[3];
    const float* khigh = (const float*)d_in[4];
    const float* emean = (const float*)d_in[5];
    const float* elow  = (const float*)d_in[6];
    const float* ehigh = (const float*)d_in[7];
    const float* pol   = (const float*)d_in[8];
    float* out = (float*)d_out;

    k_prep<<<KNOTS, 128>>>(x, sw, kmean, klow, khigh, elow, ehigh, pol);
    k_mix<<<KNOTS, 256>>>(emean);
    k_reduce<<<1, 1024>>>(sw);
    k_out<<<(S_PTS + 127) / 128, 128>>>(x, sw, out);
}